// round 16
// baseline (speedup 1.0000x reference)
#include <cuda_runtime.h>
#include <math.h>

#define BB    256
#define T2V   1026
#define TP1   1025
#define NVOC  35
#define H7    224
#define HN    (BB*1024)
#define EPSV  2.220446049250313e-16f
#define LOG2E 1.4426950408889634f
#define LN2   0.6931471805599453f
#define FULLM 0xffffffffu
#define NT    256

// ---------------- device scratch (small scalars only) ----------------
static __device__ float g_prex[NVOC * H7];
static __device__ float g_intA[BB], g_intB[BB], g_mskA[BB], g_mskB[BB];
static __device__ float g_loglam[BB], g_nev[BB];

// ---------------- fast math ----------------
__device__ __forceinline__ float ex2f(float x){ float r; asm("ex2.approx.f32 %0,%1;":"=f"(r):"f"(x)); return r; }
__device__ __forceinline__ float lg2f(float x){ float r; asm("lg2.approx.f32 %0,%1;":"=f"(r):"f"(x)); return r; }
__device__ __forceinline__ float rcpf(float x){ float r; asm("rcp.approx.f32 %0,%1;":"=f"(r):"f"(x)); return r; }
__device__ __forceinline__ float sig_fast(float x){
    float s = ex2f(-fabsf(x) * LOG2E);
    float r = rcpf(1.0f + s);
    return x >= 0.0f ? r : s * r;
}
__device__ __forceinline__ float tanh_fast(float x){
    float s2 = ex2f(-2.0f * LOG2E * fabsf(x));
    float tv = (1.0f - s2) * rcpf(1.0f + s2);
    return x >= 0.0f ? tv : -tv;
}
__device__ __forceinline__ float softplus_fast(float x){
    return fmaxf(x, 0.0f) + lg2f(1.0f + ex2f(-fabsf(x) * LOG2E)) * LN2;
}
__device__ __forceinline__ float softplus_log2(float x){   // softplus(x)/ln2
    return fmaxf(x, 0.0f) * LOG2E + lg2f(1.0f + ex2f(-fabsf(x) * LOG2E));
}
__device__ __forceinline__ unsigned su32(const void* p){
    unsigned a;
    asm("{ .reg .u64 t; cvta.to.shared.u64 t, %1; cvt.u32.u64 %0, t; }" : "=r"(a) : "l"(p));
    return a;
}

// ---------------- SMEM layout (float offsets; 16B-aligned blocks) ----------
// two batches per CTA: ring/row arrays have a second copy at fixed stride
#define OFF_PREX 0        /* 7840 */
#define OFF_RC   7840     /* 2 x 2048 */
#define OFF_RCB  11936
#define OFF_RL   16032
#define OFF_RO   20128
#define OFF_RH   24224
#define OFF_DT   28320    /* 2 x 1028 */
#define OFF_EV   30376
#define OFF_DTS  32432
#define OFF_MSK  34488
#define OFF_WLP  36544    /* 1056 */
#define OFF_ACT  37600    /* 2 x 224 */
#define OFF_H    38048    /* 2 x 32 */
#define OFF_SHCH 38112    /* 8 x 32 */
#define OFF_RED  38368    /* 8 */
#define SMEM_FLOATS 38376
#define SMEM_BYTES  (SMEM_FLOATS * 4)

// ---------------- kernel A: prex[v][j] = Emb[v]·Wx[:,j] + b[j] -------------
__global__ void k_prex(const float* __restrict__ Emb,
                       const float* __restrict__ W,
                       const float* __restrict__ bias) {
    int v = blockIdx.x;
    int j = threadIdx.x;
    float acc = bias[j];
    #pragma unroll
    for (int k = 0; k < 32; k++)
        acc += Emb[v * 32 + k] * W[k * H7 + j];
    g_prex[v * H7 + j] = acc;
}

// ---------------- kernel B: two-batch phase-interleaved scan ---------------
// warps 0-6: uniform gate warps (one packed dot per phase, alternating batch)
// warp 7   : dedicated cell-update (phase 2) warp, alternating batch
// One __syncthreads per batch-step; 128 CTAs -> <=1 CTA/SM.
__global__ void __launch_bounds__(NT, 1)
k_scan(const int*   __restrict__ event,
       const float* __restrict__ dtime,
       const float* __restrict__ W,
       const float* __restrict__ Wl,
       const float* __restrict__ dts,
       const float* __restrict__ mask,
       float*       __restrict__ lam_out) {
    extern __shared__ float sm[];
    const int cb   = blockIdx.x;            // 0..127
    const int b0   = 2 * cb, b1 = 2 * cb + 1;
    const int j    = threadIdx.x;
    const int w    = j >> 5;
    const int lane = j & 31;

    float* prex  = sm + OFF_PREX;
    float* ringc = sm + OFF_RC;
    float* ringcb= sm + OFF_RCB;
    float* ringL = sm + OFF_RL;
    float* ringo = sm + OFF_RO;
    float* ringh = sm + OFF_RH;
    float* dt_sh = sm + OFF_DT;
    int*   ev_sh = (int*)(sm + OFF_EV);
    float* dts_sh= sm + OFF_DTS;
    float* msk_sh= sm + OFF_MSK;
    float* wlp   = sm + OFF_WLP;
    float* act   = sm + OFF_ACT;      // [2][224]
    float* h_sh  = sm + OFF_H;        // [2][32]
    float* shch  = sm + OFF_SHCH;     // [8][32]
    float* red   = sm + OFF_RED;

    // -------- init: stage everything into SMEM once --------
    for (int i = j; i < NVOC * H7; i += NT) prex[i] = g_prex[i];
    for (int i = j; i < T2V; i += NT) {
        dt_sh[i]        = dtime[b0 * T2V + i];
        dt_sh[1028 + i] = dtime[b1 * T2V + i];
        ev_sh[i]        = event[b0 * T2V + i];
        ev_sh[1028 + i] = event[b1 * T2V + i];
    }
    const int f00 = b0 * TP1, f01 = b1 * TP1;
    for (int i = j; i < TP1; i += NT) {
        bool ok0 = (f00 + i) < HN, ok1 = (f01 + i) < HN;
        dts_sh[i]        = ok0 ? dts[f00 + i]  : 0.0f;
        dts_sh[1028 + i] = ok1 ? dts[f01 + i]  : 0.0f;
        msk_sh[i]        = ok0 ? mask[f00 + i] : 0.0f;
        msk_sh[1028 + i] = ok1 ? mask[f01 + i] : 0.0f;
    }
    for (int i = j; i < 1024; i += NT)
        wlp[(i >> 5) * 33 + (i & 31)] = Wl[i];

    // packed recurrent weight column (gate warps): wp[k]=(W_h[2k][j],W_h[2k+1][j])
    unsigned long long wp[16];
    if (w < 7) {
        #pragma unroll
        for (int k = 0; k < 16; k++) {
            float wlo = W[(32 + 2 * k)     * H7 + j];
            float whi = W[(32 + 2 * k + 1) * H7 + j];
            asm("mov.b64 %0, {%1,%2};" : "=l"(wp[k]) : "f"(wlo), "f"(whi));
        }
    }

    // sampler weights (all 8 warps participate in chunks)
    float wle[32];
    {
        const float4* wl4 = (const float4*)(Wl + lane * 32);
        #pragma unroll
        for (int p = 0; p < 8; p++) {
            float4 wv = wl4[p];
            wle[4*p+0] = wv.x; wle[4*p+1] = wv.y;
            wle[4*p+2] = wv.z; wle[4*p+3] = wv.w;
        }
    }

    if (j < 64) h_sh[j] = 0.0f;
    // carries live in warp 7
    float cmA = 0.f, cbmA = 0.f, cmB = 0.f, cbmB = 0.f;
    // per-batch accumulators
    float accL0 = 0.f, accN0 = 0.f, ai0_0 = 0.f, ai1_0 = 0.f, am0_0 = 0.f, am1_0 = 0.f;
    float accL1 = 0.f, accN1 = 0.f, ai0_1 = 0.f, ai1_1 = 0.f, am0_1 = 0.f, am1_1 = 0.f;

    const unsigned hbase = su32(h_sh);

    __syncthreads();

    float pxA = 0.f, pxB = 0.f;
    if (w < 7) {
        pxA = prex[ev_sh[0] * H7 + j];
        pxB = prex[ev_sh[1028] * H7 + j];
    }

    // -------- gate-warp dot + activation for batch X at step t -------------
    auto dot_act = [&](int X, int t) {
        unsigned hb = hbase + X * 128;
        float pxv = X ? pxB : pxA;
        unsigned long long p0, p1, p2, p3;
        asm("mov.b64 %0, {%1,%2};" : "=l"(p0) : "f"(pxv), "f"(0.0f));
        asm("mov.b64 %0, 0;" : "=l"(p1));
        asm("mov.b64 %0, 0;" : "=l"(p2));
        asm("mov.b64 %0, 0;" : "=l"(p3));
        #pragma unroll
        for (int q = 0; q < 4; q++) {
            unsigned long long hA, hB2, hC, hD;
            asm volatile("ld.shared.v2.b64 {%0,%1},[%2];" : "=l"(hA), "=l"(hB2) : "r"(hb + 32 * q));
            asm volatile("ld.shared.v2.b64 {%0,%1},[%2];" : "=l"(hC), "=l"(hD) : "r"(hb + 32 * q + 16));
            asm("fma.rn.f32x2 %0,%1,%2,%0;" : "+l"(p0) : "l"(hA),  "l"(wp[4*q+0]));
            asm("fma.rn.f32x2 %0,%1,%2,%0;" : "+l"(p1) : "l"(hB2), "l"(wp[4*q+1]));
            asm("fma.rn.f32x2 %0,%1,%2,%0;" : "+l"(p2) : "l"(hC),  "l"(wp[4*q+2]));
            asm("fma.rn.f32x2 %0,%1,%2,%0;" : "+l"(p3) : "l"(hD),  "l"(wp[4*q+3]));
        }
        asm("add.rn.f32x2 %0,%0,%1;" : "+l"(p0) : "l"(p1));
        asm("add.rn.f32x2 %0,%0,%1;" : "+l"(p2) : "l"(p3));
        asm("add.rn.f32x2 %0,%0,%1;" : "+l"(p0) : "l"(p2));
        float plo, phi;
        asm("mov.b64 {%0,%1},%2;" : "=f"(plo), "=f"(phi) : "l"(p0));
        float pre = plo + phi;

        float a;
        if (w == 2)      a = tanh_fast(pre);       // z
        else if (w == 6) a = softplus_log2(pre);   // delta (log2 domain)
        else             a = sig_fast(pre);        // i,f,o,ib,fb
        act[X * 224 + j] = a;

        if (t < TP1 - 1) {
            float np = prex[ev_sh[X * 1028 + t + 1] * H7 + j];
            if (X) pxB = np; else pxA = np;
        }
    };

    // -------- warp-7 cell update for batch X at step t ---------------------
    auto ph2 = [&](int X, int t) {
        const float* A = act + X * 224;
        float iv  = A[lane];
        float fv  = A[32  + lane];
        float zv  = A[64  + lane];
        float ov  = A[96  + lane];
        float ibv = A[128 + lane];
        float fbv = A[160 + lane];
        float L   = A[192 + lane];
        float dtv = dt_sh[X * 1028 + t + 1];
        float e   = ex2f(-L * dtv);

        float cm  = X ? cmB  : cmA;
        float cbm = X ? cbmB : cbmA;
        float c  = fmaf(fv,  cm,  iv  * zv);
        float cb = fmaf(fbv, cbm, ibv * zv);
        float cn = fmaf(c - cb, e, cb);
        float h  = ov * tanh_fast(cn);

        int sl = (t & 63) * 32 + lane + X * 2048;
        h_sh[X * 32 + lane] = h;
        ringc [sl] = c;
        ringcb[sl] = cb;
        ringL [sl] = L;
        ringo [sl] = ov;
        ringh [sl] = h;

        if (X) { cmB = cn; cbmB = cb; } else { cmA = cn; cbmA = cb; }
    };

    // -------- chunk: sampling + target for batch X, steps [t0, t0+cnt) -----
    auto chunk = [&](int X, int gb, int t0, int cnt) {
        const int f0      = gb * TP1;
        const int validTp = (HN - f0 < TP1) ? (HN - f0) : TP1;
        const int*   evX  = ev_sh  + X * 1028;
        const float* dtsX = dts_sh + X * 1028;
        const float* mskX = msk_sh + X * 1028;

        for (int rr = w; rr < cnt; rr += 8) {
            int trow = t0 + rr;
            int base = (trow & 63) * 32 + lane + X * 2048;

            // ---- target log-lambda ----
            {
                int tgt = evX[trow + 1];
                bool mm = (tgt < 32);
                int  tt = mm ? tgt : 0;
                float p = ringh[base] * wlp[tt * 33 + lane];
                #pragma unroll
                for (int o = 16; o > 0; o >>= 1) p += __shfl_down_sync(FULLM, p, o);
                if (lane == 0 && mm) {
                    float v = lg2f(softplus_fast(p) + EPSV) * LN2;
                    if (X) { accL1 += v; accN1 += 1.0f; }
                    else   { accL0 += v; accN0 += 1.0f; }
                }
            }
            // ---- MC sample row ----
            if (trow < validTp) {
                float c  = ringc [base];
                float cb = ringcb[base];
                float L  = ringL [base];
                float o  = ringo [base];
                float dtv = dtsX[trow];
                float m   = mskX[trow];

                float cd = fmaf(c - cb, ex2f(-L * dtv), cb);
                float ch = o * tanh_fast(cd);
                shch[w * 32 + lane] = ch;
                __syncwarp();

                float d0 = 0.f, d1 = 0.f, d2 = 0.f, d3 = 0.f;
                const float4* c4 = (const float4*)(shch + w * 32);
                #pragma unroll
                for (int p = 0; p < 8; p++) {
                    float4 cv = c4[p];
                    d0 = fmaf(cv.x, wle[4*p+0], d0);
                    d1 = fmaf(cv.y, wle[4*p+1], d1);
                    d2 = fmaf(cv.z, wle[4*p+2], d2);
                    d3 = fmaf(cv.w, wle[4*p+3], d3);
                }
                float sp = softplus_fast((d0 + d1) + (d2 + d3));
                lam_out[(size_t)(f0 + trow) * 32 + lane] = sp;

                bool g0 = (gb + trow < 1024);
                float sm_ = sp * m;
                if (X) { if (g0) { ai0_1 += sm_; if (lane==0) am0_1 += m; }
                         else    { ai1_1 += sm_; if (lane==0) am1_1 += m; } }
                else   { if (g0) { ai0_0 += sm_; if (lane==0) am0_0 += m; }
                         else    { ai1_0 += sm_; if (lane==0) am1_0 += m; } }
                __syncwarp();
            }
        }
    };

    // ---------------- main loop: P1 / P2 phase interleave -------------------
    for (int t = 0; t < TP1; t++) {
        // P1: dotA(t) || ph2B(t-1)
        if (w < 7) dot_act(0, t);
        else if (t > 0) ph2(1, t - 1);
        __syncthreads();

        if ((t & 63) == 0 && t) {              // both rings hold [t-64, t-1]
            chunk(0, b0, t - 64, 64);
            chunk(1, b1, t - 64, 64);
            __syncthreads();
        }

        // P2: dotB(t) || ph2A(t)
        if (w < 7) dot_act(1, t);
        else ph2(0, t);
        __syncthreads();
    }

    // drain: ph2B(1024), then last chunk row for both batches
    if (w == 7) ph2(1, 1024);
    __syncthreads();
    chunk(0, b0, 1024, 1);
    chunk(1, b1, 1024, 1);
    __syncthreads();

    // ---------------- epilogue: block reductions (8 warps) -----------------
    auto bred = [&](float v) -> float {
        #pragma unroll
        for (int o = 16; o > 0; o >>= 1) v += __shfl_down_sync(FULLM, v, o);
        if (lane == 0) red[w] = v;
        __syncthreads();
        float r = 0.0f;
        if (j == 0) {
            #pragma unroll
            for (int k = 0; k < 8; k++) r += red[k];
        }
        __syncthreads();
        return r;
    };

    float s;
    s = bred(ai0_0); if (j == 0) g_intA[b0] = s;
    s = bred(ai1_0); if (j == 0) g_intB[b0] = s;
    s = bred(am0_0); if (j == 0) g_mskA[b0] = s;
    s = bred(am1_0); if (j == 0) g_mskB[b0] = s;
    s = bred(accL0); if (j == 0) g_loglam[b0] = s;
    s = bred(accN0); if (j == 0) g_nev[b0] = s;
    s = bred(ai0_1); if (j == 0) g_intA[b1] = s;
    s = bred(ai1_1); if (j == 0) g_intB[b1] = s;
    s = bred(am0_1); if (j == 0) g_mskA[b1] = s;
    s = bred(am1_1); if (j == 0) g_mskB[b1] = s;
    s = bred(accL1); if (j == 0) g_loglam[b1] = s;
    s = bred(accN1); if (j == 0) g_nev[b1] = s;
}

// ---------------- final: stitch integral groups + reduce scalars ----------
__global__ void __launch_bounds__(256)
k_final(const float* __restrict__ dur, float* __restrict__ out) {
    const int bb = threadIdx.x;     // one thread per group
    __shared__ float red[8];

    float lamsum = g_intA[bb] + (bb > 0 ? g_intB[bb - 1] : 0.0f);
    float msum   = g_mskA[bb] + (bb > 0 ? g_mskB[bb - 1] : 0.0f);
    float integ  = __fdividef(lamsum, msum) * dur[bb];
    float lp = g_loglam[bb] - integ;
    float nv = g_nev[bb];

    int wid = threadIdx.x >> 5, lid = threadIdx.x & 31;
    #pragma unroll
    for (int o = 16; o > 0; o >>= 1) lp += __shfl_down_sync(FULLM, lp, o);
    if (lid == 0) red[wid] = lp;
    __syncthreads();
    if (wid == 0) {
        float v = (lid < 8) ? red[lid] : 0.0f;
        #pragma unroll
        for (int o = 4; o > 0; o >>= 1) v += __shfl_down_sync(FULLM, v, o);
        if (lid == 0) out[0] = -v;
    }
    __syncthreads();
    #pragma unroll
    for (int o = 16; o > 0; o >>= 1) nv += __shfl_down_sync(FULLM, nv, o);
    if (lid == 0) red[wid] = nv;
    __syncthreads();
    if (wid == 0) {
        float v = (lid < 8) ? red[lid] : 0.0f;
        #pragma unroll
        for (int o = 4; o > 0; o >>= 1) v += __shfl_down_sync(FULLM, v, o);
        if (lid == 0) out[1] = v;
    }
}

// ---------------- launch ----------------
extern "C" void kernel_launch(void* const* d_in, const int* in_sizes, int n_in,
                              void* d_out, int out_size) {
    const int*   event = (const int*)  d_in[0];
    const float* dtime = (const float*)d_in[1];
    const float* dur   = (const float*)d_in[2];
    const float* dts   = (const float*)d_in[3];
    // d_in[4] = index_of_hidden_sampling (unused by the reference)
    const float* mask  = (const float*)d_in[5];
    const float* Emb   = (const float*)d_in[6];
    const float* W     = (const float*)d_in[7];
    const float* bias  = (const float*)d_in[8];
    const float* Wl    = (const float*)d_in[9];

    float* out = (float*)d_out;
    long long lam_elems = (long long)HN * 32;
    long long lamoff = (long long)out_size - lam_elems;
    if (lamoff < 0) lamoff = 0;
    float* lam_out = out + lamoff;

    static int attr_set = 0;
    if (!attr_set) {
        cudaFuncSetAttribute(k_scan, cudaFuncAttributeMaxDynamicSharedMemorySize,
                             SMEM_BYTES);
        attr_set = 1;
    }

    k_prex <<<NVOC, H7>>>(Emb, W, bias);
    k_scan <<<BB / 2, NT, SMEM_BYTES>>>(event, dtime, W, Wl, dts, mask, lam_out);
    k_final<<<1, 256>>>(dur, out);
}

// round 17
// speedup vs baseline: 1.3815x; 1.3815x over previous
#include <cuda_runtime.h>
#include <math.h>

#define BB    256
#define T2V   1026
#define TP1   1025
#define NVOC  35
#define H7    224
#define HN    (BB*1024)
#define EPSV  2.220446049250313e-16f
#define LOG2E 1.4426950408889634f
#define LN2   0.6931471805599453f
#define FULLM 0xffffffffu

// ---------------- device scratch (small scalars only) ----------------
static __device__ float g_prex[NVOC * H7];
static __device__ float g_intA[BB], g_intB[BB], g_mskA[BB], g_mskB[BB];
static __device__ float g_loglam[BB], g_nev[BB];

// ---------------- fast math ----------------
__device__ __forceinline__ float ex2f(float x){ float r; asm("ex2.approx.f32 %0,%1;":"=f"(r):"f"(x)); return r; }
__device__ __forceinline__ float lg2f(float x){ float r; asm("lg2.approx.f32 %0,%1;":"=f"(r):"f"(x)); return r; }
__device__ __forceinline__ float rcpf(float x){ float r; asm("rcp.approx.f32 %0,%1;":"=f"(r):"f"(x)); return r; }
__device__ __forceinline__ float sig_fast(float x){
    float s = ex2f(-fabsf(x) * LOG2E);
    float r = rcpf(1.0f + s);
    return x >= 0.0f ? r : s * r;
}
__device__ __forceinline__ float tanh_fast(float x){
    float s2 = ex2f(-2.0f * LOG2E * fabsf(x));
    float tv = (1.0f - s2) * rcpf(1.0f + s2);
    return x >= 0.0f ? tv : -tv;
}
__device__ __forceinline__ float softplus_fast(float x){
    return fmaxf(x, 0.0f) + lg2f(1.0f + ex2f(-fabsf(x) * LOG2E)) * LN2;
}
__device__ __forceinline__ float softplus_log2(float x){   // softplus(x)/ln2
    return fmaxf(x, 0.0f) * LOG2E + lg2f(1.0f + ex2f(-fabsf(x) * LOG2E));
}
__device__ __forceinline__ unsigned su32(const void* p){
    unsigned a;
    asm("{ .reg .u64 t; cvta.to.shared.u64 t, %1; cvt.u32.u64 %0, t; }" : "=r"(a) : "l"(p));
    return a;
}

// ---------------- SMEM layout (float offsets; 16B-aligned blocks) ----------
#define OFF_PREX 0        /* 35*224 = 7840 */
#define OFF_RC   7840     /* ring c     64*32 */
#define OFF_RCB  9888     /* ring cbar  64*32 */
#define OFF_RL   11936    /* ring delta 64*32 */
#define OFF_RO   13984    /* ring o     64*32 */
#define OFF_RH   16032    /* ring h     64*32 */
#define OFF_DT   18080    /* dtime row 1026 (+pad) */
#define OFF_EV   19108    /* event row 1026 (int) */
#define OFF_DTS  20136    /* dts row  1025 (+pad) */
#define OFF_MSK  21164    /* mask row 1025 (+pad) */
#define OFF_WLP  22192    /* Wl padded 32*33 */
#define OFF_ACT  23248    /* act 224 */
#define OFF_H    23472    /* h vector 32 */
#define OFF_E    23504    /* decay e 32 */
#define OFF_SHCH 23536    /* per-warp ch transpose 7*32 */
#define OFF_RED  23760    /* reduction 8 */
#define SMEM_FLOATS 23776
#define SMEM_BYTES  (SMEM_FLOATS * 4)

// ---------------- kernel A: prex[v][j] = Emb[v]·Wx[:,j] + b[j] -------------
__global__ void k_prex(const float* __restrict__ Emb,
                       const float* __restrict__ W,
                       const float* __restrict__ bias) {
    int v = blockIdx.x;
    int j = threadIdx.x;
    float acc = bias[j];
    #pragma unroll
    for (int k = 0; k < 32; k++)
        acc += Emb[v * 32 + k] * W[k * H7 + j];
    g_prex[v * H7 + j] = acc;
}

// ---------------- kernel B: fused scan + chunked consumers (R12 core) ------
__global__ void __launch_bounds__(224, 2)
k_scan(const int*   __restrict__ event,
       const float* __restrict__ dtime,
       const float* __restrict__ W,
       const float* __restrict__ Wl,
       const float* __restrict__ dts,
       const float* __restrict__ mask,
       float*       __restrict__ lam_out) {
    extern __shared__ float sm[];
    const int b    = blockIdx.x;
    const int j    = threadIdx.x;
    const int w    = j >> 5;
    const int lane = j & 31;

    float* prex  = sm + OFF_PREX;
    float* ringc = sm + OFF_RC;
    float* ringcb= sm + OFF_RCB;
    float* ringL = sm + OFF_RL;
    float* ringo = sm + OFF_RO;
    float* ringh = sm + OFF_RH;
    float* dt_sh = sm + OFF_DT;
    int*   ev_sh = (int*)(sm + OFF_EV);
    float* dts_sh= sm + OFF_DTS;
    float* msk_sh= sm + OFF_MSK;
    float* wlp   = sm + OFF_WLP;
    float* act   = sm + OFF_ACT;
    float* h_sh  = sm + OFF_H;
    float* e_sh  = sm + OFF_E;
    float* shch  = sm + OFF_SHCH;
    float* red   = sm + OFF_RED;

    const int f0      = b * TP1;
    const int validTp = (HN - f0 < TP1) ? (HN - f0) : TP1;

    // -------- init: stage everything into SMEM once --------
    for (int i = j; i < NVOC * H7; i += H7) prex[i] = g_prex[i];
    for (int i = j; i < T2V; i += H7) {
        dt_sh[i] = dtime[b * T2V + i];
        ev_sh[i] = event[b * T2V + i];
    }
    for (int i = j; i < TP1; i += H7) {
        bool ok = (f0 + i) < HN;
        dts_sh[i] = ok ? dts[f0 + i]  : 0.0f;
        msk_sh[i] = ok ? mask[f0 + i] : 0.0f;
    }
    for (int i = j; i < 1024; i += H7)
        wlp[(i >> 5) * 33 + (i & 31)] = Wl[i];

    // packed recurrent weight column: wp[k] = (W_h[2k][j], W_h[2k+1][j])
    unsigned long long wp[16];
    #pragma unroll
    for (int k = 0; k < 16; k++) {
        float wlo = W[(32 + 2 * k)     * H7 + j];
        float whi = W[(32 + 2 * k + 1) * H7 + j];
        asm("mov.b64 %0, {%1,%2};" : "=l"(wp[k]) : "f"(wlo), "f"(whi));
    }

    // sampler weights: lane e keeps Wl[e][:]
    float wle[32];
    {
        const float4* wl4 = (const float4*)(Wl + lane * 32);
        #pragma unroll
        for (int p = 0; p < 8; p++) {
            float4 wv = wl4[p];
            wle[4*p+0] = wv.x; wle[4*p+1] = wv.y;
            wle[4*p+2] = wv.z; wle[4*p+3] = wv.w;
        }
    }

    if (j < 32) h_sh[j] = 0.0f;
    float cm = 0.0f, cbm = 0.0f;               // carries (warp 0)
    float acc0 = 0.f, acc1 = 0.f, am0 = 0.f, am1 = 0.f;  // integral groups
    float accL = 0.f, accN = 0.f;              // target loglambda

    const unsigned hb = su32(h_sh);

    __syncthreads();

    float px = prex[ev_sh[0] * H7 + j];

    // -------- chunk processor: sampling + target for steps [t0, t0+cnt) ----
    auto chunk = [&](int t0, int cnt) {
        for (int rr = w; rr < cnt; rr += 7) {
            int trow = t0 + rr;
            int base = (trow & 63) * 32 + lane;

            // ---- target log-lambda (all steps) ----
            {
                int tgt = ev_sh[trow + 1];
                bool mm = (tgt < 32);
                int  tt = mm ? tgt : 0;
                float p = ringh[base] * wlp[tt * 33 + lane];
                #pragma unroll
                for (int o = 16; o > 0; o >>= 1) p += __shfl_down_sync(FULLM, p, o);
                if (lane == 0 && mm) {
                    accL += lg2f(softplus_fast(p) + EPSV) * LN2;
                    accN += 1.0f;
                }
            }
            // ---- MC sample row (only valid flat rows) ----
            if (trow < validTp) {
                float c  = ringc [base];
                float cb = ringcb[base];
                float L  = ringL [base];
                float o  = ringo [base];
                float dtv = dts_sh[trow];
                float m   = msk_sh[trow];

                float cd = fmaf(c - cb, ex2f(-L * dtv), cb);
                float ch = o * tanh_fast(cd);
                shch[w * 32 + lane] = ch;
                __syncwarp();

                float d0 = 0.f, d1 = 0.f, d2 = 0.f, d3 = 0.f;
                const float4* c4 = (const float4*)(shch + w * 32);
                #pragma unroll
                for (int p = 0; p < 8; p++) {
                    float4 cv = c4[p];                 // broadcast
                    d0 = fmaf(cv.x, wle[4*p+0], d0);
                    d1 = fmaf(cv.y, wle[4*p+1], d1);
                    d2 = fmaf(cv.z, wle[4*p+2], d2);
                    d3 = fmaf(cv.w, wle[4*p+3], d3);
                }
                float sp = softplus_fast((d0 + d1) + (d2 + d3));
                lam_out[(size_t)(f0 + trow) * 32 + lane] = sp;

                if (b + trow < 1024) { acc0 += sp * m; if (lane == 0) am0 += m; }
                else                 { acc1 += sp * m; if (lane == 0) am1 += m; }
                __syncwarp();
            }
        }
    };

    // -------- one scan step (R12 core + straggler trims) -------------------
    auto step = [&](int t, bool last) {
        int sl = (t & 63) * 32 + lane;

        // phase 1: packed-f32x2 dot + gate nonlinearity
        unsigned long long pacc0, pacc1, pacc2, pacc3;
        asm("mov.b64 %0, {%1,%2};" : "=l"(pacc0) : "f"(px), "f"(0.0f));
        asm("mov.b64 %0, 0;" : "=l"(pacc1));
        asm("mov.b64 %0, 0;" : "=l"(pacc2));
        asm("mov.b64 %0, 0;" : "=l"(pacc3));
        #pragma unroll
        for (int q = 0; q < 4; q++) {
            unsigned long long hA, hB, hC, hD;
            asm volatile("ld.shared.v2.b64 {%0,%1},[%2];" : "=l"(hA), "=l"(hB) : "r"(hb + 32 * q));
            asm volatile("ld.shared.v2.b64 {%0,%1},[%2];" : "=l"(hC), "=l"(hD) : "r"(hb + 32 * q + 16));
            asm("fma.rn.f32x2 %0,%1,%2,%0;" : "+l"(pacc0) : "l"(hA), "l"(wp[4*q+0]));
            asm("fma.rn.f32x2 %0,%1,%2,%0;" : "+l"(pacc1) : "l"(hB), "l"(wp[4*q+1]));
            asm("fma.rn.f32x2 %0,%1,%2,%0;" : "+l"(pacc2) : "l"(hC), "l"(wp[4*q+2]));
            asm("fma.rn.f32x2 %0,%1,%2,%0;" : "+l"(pacc3) : "l"(hD), "l"(wp[4*q+3]));
        }
        asm("add.rn.f32x2 %0,%0,%1;" : "+l"(pacc0) : "l"(pacc1));
        asm("add.rn.f32x2 %0,%0,%1;" : "+l"(pacc2) : "l"(pacc3));
        asm("add.rn.f32x2 %0,%0,%1;" : "+l"(pacc0) : "l"(pacc2));
        float plo, phi;
        asm("mov.b64 {%0,%1},%2;" : "=f"(plo), "=f"(phi) : "l"(pacc0));
        float pre = plo + phi;

        float a;
        if (w == 2) {                          // z: tanh (uniform per warp)
            a = tanh_fast(pre);
            act[j] = a;
        } else if (w == 6) {                   // delta: softplus, log2 domain
            a = softplus_log2(pre);
            e_sh[lane] = ex2f(-a * dt_sh[t + 1]);   // decay for THIS step
            ringL[sl] = a;                     // act store skipped (dead)
        } else if (w == 0) {                   // i: keep in register
            a = sig_fast(pre);                 // act store skipped (own gate)
        } else {                               // f,o,ib,fb: sigmoid
            a = sig_fast(pre);
            act[j] = a;
            if (w == 3) ringo[sl] = a;
        }

        // prefetch next step's pre-x term (hidden under barrier + phase 2)
        if (!last) px = prex[ev_sh[t + 1] * H7 + j];

        __syncthreads();

        // phase 2: cell update (warp 0 only)
        if (w == 0) {
            float iv  = a;                     // own gate, register
            float fv  = act[32  + lane];
            float zv  = act[64  + lane];
            float ov  = act[96  + lane];
            float ibv = act[128 + lane];
            float fbv = act[160 + lane];
            float e   = e_sh[lane];

            float c  = fmaf(fv,  cm,  iv  * zv);
            float cb = fmaf(fbv, cbm, ibv * zv);
            float cn = fmaf(c - cb, e, cb);
            float h  = ov * tanh_fast(cn);

            h_sh[lane] = h;                    // earliest: unblocks next dot
            ringc [sl] = c;
            ringcb[sl] = cb;
            ringh [sl] = h;

            cm = cn; cbm = cb;
        }
        __syncthreads();
    };

    // ---------------- main loop: 16 blocks of 64 + 1 tail step --------------
    for (int blk = 0; blk < 16; blk++) {
        int t0 = blk * 64;
        #pragma unroll 1
        for (int i = 0; i < 64; i++) step(t0 + i, false);
        chunk(t0, 64);
        __syncthreads();                        // ring drained before overwrite
    }
    step(1024, true);
    chunk(1024, 1);
    __syncthreads();

    // ---------------- epilogue: block reductions (7 warps) -----------------
    auto bred = [&](float v) -> float {
        #pragma unroll
        for (int o = 16; o > 0; o >>= 1) v += __shfl_down_sync(FULLM, v, o);
        if (lane == 0) red[w] = v;
        __syncthreads();
        float r = 0.0f;
        if (j == 0) {
            #pragma unroll
            for (int k = 0; k < 7; k++) r += red[k];
        }
        __syncthreads();
        return r;
    };

    float s;
    s = bred(acc0); if (j == 0) g_intA[b] = s;
    s = bred(acc1); if (j == 0) g_intB[b] = s;
    s = bred(am0);  if (j == 0) g_mskA[b] = s;
    s = bred(am1);  if (j == 0) g_mskB[b] = s;
    s = bred(accL); if (j == 0) g_loglam[b] = s;
    s = bred(accN); if (j == 0) g_nev[b] = s;
}

// ---------------- final: stitch integral groups + reduce scalars ----------
__global__ void __launch_bounds__(256)
k_final(const float* __restrict__ dur, float* __restrict__ out) {
    const int bb = threadIdx.x;     // one thread per group
    __shared__ float red[8];

    float lamsum = g_intA[bb] + (bb > 0 ? g_intB[bb - 1] : 0.0f);
    float msum   = g_mskA[bb] + (bb > 0 ? g_mskB[bb - 1] : 0.0f);
    float integ  = __fdividef(lamsum, msum) * dur[bb];
    float lp = g_loglam[bb] - integ;
    float nv = g_nev[bb];

    int wid = threadIdx.x >> 5, lid = threadIdx.x & 31;
    #pragma unroll
    for (int o = 16; o > 0; o >>= 1) lp += __shfl_down_sync(FULLM, lp, o);
    if (lid == 0) red[wid] = lp;
    __syncthreads();
    if (wid == 0) {
        float v = (lid < 8) ? red[lid] : 0.0f;
        #pragma unroll
        for (int o = 4; o > 0; o >>= 1) v += __shfl_down_sync(FULLM, v, o);
        if (lid == 0) out[0] = -v;
    }
    __syncthreads();
    #pragma unroll
    for (int o = 16; o > 0; o >>= 1) nv += __shfl_down_sync(FULLM, nv, o);
    if (lid == 0) red[wid] = nv;
    __syncthreads();
    if (wid == 0) {
        float v = (lid < 8) ? red[lid] : 0.0f;
        #pragma unroll
        for (int o = 4; o > 0; o >>= 1) v += __shfl_down_sync(FULLM, v, o);
        if (lid == 0) out[1] = v;
    }
}

// ---------------- launch ----------------
extern "C" void kernel_launch(void* const* d_in, const int* in_sizes, int n_in,
                              void* d_out, int out_size) {
    const int*   event = (const int*)  d_in[0];
    const float* dtime = (const float*)d_in[1];
    const float* dur   = (const float*)d_in[2];
    const float* dts   = (const float*)d_in[3];
    // d_in[4] = index_of_hidden_sampling (unused by the reference)
    const float* mask  = (const float*)d_in[5];
    const float* Emb   = (const float*)d_in[6];
    const float* W     = (const float*)d_in[7];
    const float* bias  = (const float*)d_in[8];
    const float* Wl    = (const float*)d_in[9];

    float* out = (float*)d_out;
    long long lam_elems = (long long)HN * 32;
    long long lamoff = (long long)out_size - lam_elems;
    if (lamoff < 0) lamoff = 0;
    float* lam_out = out + lamoff;

    static int attr_set = 0;
    if (!attr_set) {
        cudaFuncSetAttribute(k_scan, cudaFuncAttributeMaxDynamicSharedMemorySize,
                             SMEM_BYTES);
        attr_set = 1;
    }

    k_prex <<<NVOC, H7>>>(Emb, W, bias);
    k_scan <<<BB, H7, SMEM_BYTES>>>(event, dtime, W, Wl, dts, mask, lam_out);
    k_final<<<1, 256>>>(dur, out);
}